// round 3
// baseline (speedup 1.0000x reference)
#include <cuda_runtime.h>
#include <math.h>

#define NPTS   50000
#define BATCH  32
#define MAXDEG 16
#define ROWF   96            // floats per node row in delta_t: 3 comps * 32 batches
#define GRID_B 1184          // blocks for main kernel (148 SMs * 8)

// Scratch: delta_t[(N+1)][3][32]  (pad row at index NPTS is zero)
__device__ float g_delta[(NPTS + 1) * ROWF];
__device__ float g_part[GRID_B];

// ---------------------------------------------------------------------------
// Kernel A: delta = predict - gt, transposed to [node][comp][batch].
// Block handles 64 consecutive nodes. smem tile [32 batches][64*3 floats],
// padded row pitch 193 for conflict-free transposed reads.
// ---------------------------------------------------------------------------
__global__ void __launch_bounds__(256) kA_delta_transpose(
    const float* __restrict__ pred, const float* __restrict__ gt)
{
    __shared__ float tile[BATCH][64 * 3 + 1];   // pitch 193

    int node0 = blockIdx.x * 64;
    int cnt = NPTS - node0; if (cnt > 64) cnt = 64;
    int ne = cnt * 3;

    // Read phase: contiguous per batch
    for (int b = 0; b < BATCH; b++) {
        const float* p = pred + (size_t)b * NPTS * 3 + (size_t)node0 * 3;
        const float* q = gt   + (size_t)b * NPTS * 3 + (size_t)node0 * 3;
        for (int i = threadIdx.x; i < ne; i += blockDim.x)
            tile[b][i] = p[i] - q[i];
    }
    __syncthreads();

    // Write phase: linear over output rows [node][c*32 + b]
    int total = cnt * ROWF;
    for (int o = threadIdx.x; o < total; o += blockDim.x) {
        int nl = o / ROWF;
        int r  = o % ROWF;
        int c  = r >> 5;          // component
        int b  = r & 31;          // batch
        g_delta[(size_t)(node0 + nl) * ROWF + r] = tile[b][nl * 3 + c];
    }

    // Zero pad row (node index == NPTS)
    if (blockIdx.x == 0) {
        for (int i = threadIdx.x; i < ROWF; i += blockDim.x)
            g_delta[(size_t)NPTS * ROWF + i] = 0.0f;
    }
}

// ---------------------------------------------------------------------------
// Kernel B: per-node laplacian diff, per-(b,node) norm, block partial sums.
// 384 threads = 4 groups of 96 (3 warps each). Group handles one node/iter.
// Thread t in group: c = t/32 (warp), b = t%32 (lane) -> each warp reads one
// full 128B line of every gathered 384B row.
// NOTE: neighbour buffer is int32 on the wire (JAX downgrades int64 without
// x64 mode). Indices additionally clamped to [0, NPTS] as a fault guard.
// ---------------------------------------------------------------------------
__global__ void __launch_bounds__(384) kB_laplace_norm(
    const int* __restrict__ nbr, const int* __restrict__ deg)
{
    __shared__ float s_sq[384];
    __shared__ int   s_nbr[4][MAXDEG];
    __shared__ float s_deg[4];
    __shared__ float s_part[4];

    const int g = threadIdx.x / 96;
    const int t = threadIdx.x % 96;
    const int stride = gridDim.x * 4;
    const int iters = (NPTS + stride - 1) / stride;

    float gsum = 0.0f;

    for (int it = 0; it < iters; ++it) {
        int node = blockIdx.x * 4 + g + it * stride;
        bool active = node < NPTS;

        if (active) {
            if (t < MAXDEG) {
                int idx = nbr[(size_t)node * MAXDEG + t];
                idx = (idx < 0) ? 0 : ((idx > NPTS) ? NPTS : idx);
                s_nbr[g][t] = idx;
            }
            if (t == MAXDEG)
                s_deg[g] = (float)deg[node];
        }
        __syncthreads();

        if (active) {
            float self = g_delta[(size_t)node * ROWF + t];
            float acc  = self * s_deg[g];

            int nb[MAXDEG];
            #pragma unroll
            for (int j = 0; j < MAXDEG; j++) nb[j] = s_nbr[g][j];

            float s = 0.0f;
            #pragma unroll
            for (int j = 0; j < MAXDEG; j++)
                s += __ldg(&g_delta[(size_t)nb[j] * ROWF + t]);
            acc -= s;
            s_sq[g * 96 + t] = acc * acc;
        }
        __syncthreads();

        if (active && t < 32) {
            float v = s_sq[g * 96 + t] + s_sq[g * 96 + 32 + t] + s_sq[g * 96 + 64 + t];
            float nrm = sqrtf(v);
            #pragma unroll
            for (int o = 16; o; o >>= 1)
                nrm += __shfl_down_sync(0xffffffffu, nrm, o);
            if (t == 0) gsum += nrm;
        }
        // s_sq reads above are separated from next iteration's writes by the
        // first __syncthreads of the next iteration.
    }

    if (t == 0) s_part[g] = gsum;
    __syncthreads();
    if (threadIdx.x == 0)
        g_part[blockIdx.x] = s_part[0] + s_part[1] + s_part[2] + s_part[3];
}

// ---------------------------------------------------------------------------
// Kernel C: deterministic reduction of block partials -> loss = sum / BATCH
// ---------------------------------------------------------------------------
__global__ void __launch_bounds__(256) kC_reduce(float* __restrict__ out)
{
    __shared__ float s[256];
    float v = 0.0f;
    for (int i = threadIdx.x; i < GRID_B; i += 256)
        v += g_part[i];
    s[threadIdx.x] = v;
    __syncthreads();
    for (int o = 128; o; o >>= 1) {
        if (threadIdx.x < o) s[threadIdx.x] += s[threadIdx.x + o];
        __syncthreads();
    }
    if (threadIdx.x == 0)
        out[0] = s[0] * (1.0f / (float)BATCH);
}

// ---------------------------------------------------------------------------
extern "C" void kernel_launch(void* const* d_in, const int* in_sizes, int n_in,
                              void* d_out, int out_size)
{
    const float* pred = (const float*)d_in[0];
    const float* gt   = (const float*)d_in[1];
    const int*   nbr  = (const int*)d_in[2];
    const int*   deg  = (const int*)d_in[3];
    float*       out  = (float*)d_out;

    (void)in_sizes; (void)n_in; (void)out_size;

    int gridA = (NPTS + 63) / 64;
    kA_delta_transpose<<<gridA, 256>>>(pred, gt);
    kB_laplace_norm<<<GRID_B, 384>>>(nbr, deg);
    kC_reduce<<<1, 256>>>(out);
}

// round 5
// speedup vs baseline: 1.2891x; 1.2891x over previous
#include <cuda_runtime.h>
#include <cuda_fp16.h>
#include <math.h>

#define NPTS   50000
#define BATCH  32
#define MAXDEG 16
#define ROWH2  48            // half2 per node row: 3 comps * 16 half2 (32 batches)
#define GROUPS 8             // node-groups per block in kernel B (48 thr each)
#define GRID_B 1184

// delta_t[(N+1)][3][32] in fp16, as half2 pairs of batches. Pad row = 0.
__device__ __half2 g_delta[(NPTS + 1) * ROWH2];
__device__ float   g_part[GRID_B];

// ---------------------------------------------------------------------------
// Kernel A: delta = predict - gt, transposed to [node][comp][batch] fp16.
// Block = 32 nodes. smem tile [32 batches][96+1 floats] (pitch 97).
// ---------------------------------------------------------------------------
__global__ void __launch_bounds__(256) kA_delta_transpose(
    const float* __restrict__ pred, const float* __restrict__ gt)
{
    __shared__ float tile[BATCH][97];

    int node0 = blockIdx.x * 32;
    int cnt = NPTS - node0; if (cnt > 32) cnt = 32;
    int ne = cnt * 3;

    // Read phase: flat over (batch, element-in-segment); 96-float segments,
    // 128B-aligned (node0*12 bytes is a multiple of 384).
    for (int i = threadIdx.x; i < BATCH * 96; i += 256) {
        int b   = i / 96;
        int idx = i - b * 96;
        if (idx < ne) {
            size_t off = (size_t)b * NPTS * 3 + (size_t)node0 * 3 + idx;
            tile[b][idx] = pred[off] - gt[off];
        }
    }
    __syncthreads();

    // Write phase: coalesced half2 rows. o -> (node_l, c, p); half2 holds
    // batches {2p, 2p+1} of component c.
    for (int o = threadIdx.x; o < cnt * ROWH2; o += 256) {
        int nl = o / ROWH2;
        int r  = o - nl * ROWH2;
        int c  = r >> 4;
        int p  = r & 15;
        int col = nl * 3 + c;
        g_delta[(size_t)(node0 + nl) * ROWH2 + r] =
            __floats2half2_rn(tile[2 * p][col], tile[2 * p + 1][col]);
    }

    if (blockIdx.x == 0 && threadIdx.x < ROWH2)
        g_delta[(size_t)NPTS * ROWH2 + threadIdx.x] = __floats2half2_rn(0.f, 0.f);
}

// ---------------------------------------------------------------------------
// Kernel B: gather + laplacian diff + norms + block partials.
// 384 threads = 8 groups of 48; group handles one node per iteration.
// Thread t in group: c = t/16 (component), p = t%16 -> batches {2p, 2p+1}.
// Each group's 16-lane (c==0) segment is 16-lane aligned inside a warp.
// ---------------------------------------------------------------------------
__global__ void __launch_bounds__(384) kB_laplace_norm(
    const int* __restrict__ nbr, const int* __restrict__ deg)
{
    __shared__ float2 s_sq[GROUPS][3][16];
    __shared__ int    s_nbr[GROUPS][MAXDEG];
    __shared__ float  s_deg[GROUPS];
    __shared__ float  s_part[GROUPS];

    const int g = threadIdx.x / 48;
    const int t = threadIdx.x - g * 48;
    const int c = t >> 4;
    const int p = t & 15;
    const unsigned rmask = 0xFFFFu << ((48 * g) & 16);

    const int stride = gridDim.x * GROUPS;
    const int iters = (NPTS + stride - 1) / stride;

    float gsum = 0.0f;

    for (int it = 0; it < iters; ++it) {
        int node = blockIdx.x * GROUPS + g + it * stride;
        bool active = node < NPTS;

        if (active) {
            if (t < MAXDEG) {
                int idx = nbr[(size_t)node * MAXDEG + t];
                idx = (idx < 0) ? 0 : ((idx > NPTS) ? NPTS : idx);
                s_nbr[g][t] = idx;
            }
            if (t == MAXDEG)
                s_deg[g] = (float)deg[node];
        }
        __syncthreads();

        if (active) {
            float2 self = __half22float2(g_delta[(size_t)node * ROWH2 + t]);
            float d = s_deg[g];

            int nb[MAXDEG];
            #pragma unroll
            for (int j = 0; j < MAXDEG; j++) nb[j] = s_nbr[g][j];

            float sx = 0.f, sy = 0.f;
            #pragma unroll
            for (int j = 0; j < MAXDEG; j++) {
                float2 v = __half22float2(g_delta[(size_t)nb[j] * ROWH2 + t]);
                sx += v.x; sy += v.y;
            }
            float ax = self.x * d - sx;
            float ay = self.y * d - sy;
            s_sq[g][c][p] = make_float2(ax * ax, ay * ay);
        }
        __syncthreads();

        if (active && c == 0) {
            float2 a0 = s_sq[g][0][p];
            float2 a1 = s_sq[g][1][p];
            float2 a2 = s_sq[g][2][p];
            float nrm = sqrtf(a0.x + a1.x + a2.x) + sqrtf(a0.y + a1.y + a2.y);
            #pragma unroll
            for (int o = 8; o; o >>= 1)
                nrm += __shfl_down_sync(rmask, nrm, o, 16);
            if (p == 0) gsum += nrm;
        }
    }

    if (t == 0) s_part[g] = gsum;
    __syncthreads();
    if (threadIdx.x == 0) {
        float v = 0.f;
        #pragma unroll
        for (int i = 0; i < GROUPS; i++) v += s_part[i];
        g_part[blockIdx.x] = v;
    }
}

// ---------------------------------------------------------------------------
// Kernel C: deterministic reduction of block partials -> loss = sum / BATCH
// ---------------------------------------------------------------------------
__global__ void __launch_bounds__(256) kC_reduce(float* __restrict__ out)
{
    __shared__ float s[256];
    float v = 0.0f;
    for (int i = threadIdx.x; i < GRID_B; i += 256)
        v += g_part[i];
    s[threadIdx.x] = v;
    __syncthreads();
    for (int o = 128; o; o >>= 1) {
        if (threadIdx.x < o) s[threadIdx.x] += s[threadIdx.x + o];
        __syncthreads();
    }
    if (threadIdx.x == 0)
        out[0] = s[0] * (1.0f / (float)BATCH);
}

// ---------------------------------------------------------------------------
extern "C" void kernel_launch(void* const* d_in, const int* in_sizes, int n_in,
                              void* d_out, int out_size)
{
    const float* pred = (const float*)d_in[0];
    const float* gt   = (const float*)d_in[1];
    const int*   nbr  = (const int*)d_in[2];
    const int*   deg  = (const int*)d_in[3];
    float*       out  = (float*)d_out;

    (void)in_sizes; (void)n_in; (void)out_size;

    int gridA = (NPTS + 31) / 32;
    kA_delta_transpose<<<gridA, 256>>>(pred, gt);
    kB_laplace_norm<<<GRID_B, 384>>>(nbr, deg);
    kC_reduce<<<1, 256>>>(out);
}